// round 15
// baseline (speedup 1.0000x reference)
#include <cuda_runtime.h>
#include <cuda_fp16.h>
#include <math.h>
#include <stdint.h>

#define N 8192
#define D 128
#define NC 512
#define MAXM 64

// ---------------- scratch (device globals; no allocation allowed) ----------
__device__ __align__(16) float g_enorm[N * D];
__device__ __align__(16) __half g_h16[N * D];   // fp16(x)
__device__ int   g_cnt[NC];          // zeroed at module load; re-zeroed each run by k_final_f
__device__ int   g_members[NC * MAXM];
__device__ float g_lsep[N];
__device__ float g_samesum[N];
__device__ float g_sall[N];
__device__ float g_part[32];
__device__ int   g_pcnt[32];
__device__ unsigned g_done;          // zeroed at load; reset each run by k_final_f

// an_exp via ex2.approx with folded log2e
__device__ __forceinline__ float an_exp(float s) {
    float t = fmaxf(s + 0.4f, 0.0f);
    float x = 115.41560327111707f * t * (s - 0.4f);
    float r;
    asm("ex2.approx.f32 %0, %1;" : "=f"(r) : "f"(x));
    return r;
}

__device__ __forceinline__ uint32_t smem_u32(const void* p) {
    uint32_t a;
    asm("{ .reg .u64 t; cvta.to.shared.u64 t, %1; cvt.u32.u64 %0, t; }" : "=r"(a) : "l"(p));
    return a;
}
__device__ __forceinline__ void cpa16(uint32_t dst, const void* src) {
    asm volatile("cp.async.cg.shared.global [%0], [%1], 16;" :: "r"(dst), "l"(src) : "memory");
}
__device__ __forceinline__ void ldsm4(uint32_t* r, uint32_t addr) {
    asm volatile("ldmatrix.sync.aligned.m8n8.x4.shared.b16 {%0,%1,%2,%3}, [%4];"
        : "=r"(r[0]), "=r"(r[1]), "=r"(r[2]), "=r"(r[3]) : "r"(addr));
}
__device__ __forceinline__ void mma_f16(float* d, const uint32_t* a, uint32_t b0, uint32_t b1) {
    asm volatile(
        "mma.sync.aligned.m16n8k16.row.col.f32.f16.f16.f32 "
        "{%0,%1,%2,%3}, {%4,%5,%6,%7}, {%8,%9}, {%0,%1,%2,%3};\n"
        : "+f"(d[0]), "+f"(d[1]), "+f"(d[2]), "+f"(d[3])
        : "r"(a[0]), "r"(a[1]), "r"(a[2]), "r"(a[3]), "r"(b0), "r"(b1));
}

// per-block label dtype detect: int64 labels have all odd 32-bit words == 0
__device__ __forceinline__ int detect_is64(const void* lab, int tid) {
    int w = (tid < 64) ? ((const int*)lab)[2 * tid + 1] : 0;
    return !__syncthreads_or(w != 0);
}

// ---------------- kernel 1: normalize + fp16 + class lists (R12 proven) ----
__global__ void k_norm(const float* __restrict__ in, const void* __restrict__ lab) {
    int tid = threadIdx.x;
    int is64 = detect_is64(lab, tid);
    int gid = blockIdx.x * blockDim.x + tid;
    if (gid < N) g_sall[gid] = 0.0f;
    int row  = blockIdx.x * 8 + (tid >> 5);
    int lane = tid & 31;
    float4 v = *(const float4*)(in + row * D + lane * 4);
    float ss = v.x * v.x + v.y * v.y + v.z * v.z + v.w * v.w;
    #pragma unroll
    for (int m = 16; m >= 1; m >>= 1) ss += __shfl_xor_sync(0xffffffffu, ss, m);
    float inv = 1.0f / fmaxf(sqrtf(ss), 1e-12f);
    float o[4] = {v.x * inv, v.y * inv, v.z * inv, v.w * inv};
    float4 of; of.x = o[0]; of.y = o[1]; of.z = o[2]; of.w = o[3];
    *(float4*)(g_enorm + row * D + lane * 4) = of;
    *(__half2*)(g_h16 + row * D + lane * 4)     = __floats2half2_rn(o[0], o[1]);
    *(__half2*)(g_h16 + row * D + lane * 4 + 2) = __floats2half2_rn(o[2], o[3]);
    if (lane == 0) {
        int c = is64 ? (int)((const long long*)lab)[row] : ((const int*)lab)[row];
        int p = atomicAdd(&g_cnt[c], 1);
        if (p < MAXM) g_members[c * MAXM + p] = row;
    }
}

// ---------------- class block body (runs inside k_main_f) ------------------
__device__ void class_block(int c, char* smraw) {
    int*   mlist = (int*)smraw;
    float* se    = (float*)(smraw + 256);
    int m = g_cnt[c];
    if (m > MAXM) m = MAXM;
    int tid = threadIdx.x, lane = tid & 31, wid = tid >> 5;
    if (m == 0) return;                     // uniform across block
    if (tid < m) mlist[tid] = g_members[c * MAXM + tid];
    __syncthreads();
    for (int p = tid; p < m * D; p += 256) {
        int r = p >> 7, k = p & 127;
        se[r * 129 + k] = g_enorm[mlist[r] * D + k];
    }
    __syncthreads();
    for (int a = wid; a < m; a += 8) {
        int b0 = lane, b1 = lane + 32;
        float s0 = 0.0f, s1 = 0.0f;
        const float* ra = se + a * 129;
        #pragma unroll 8
        for (int k = 0; k < D; k++) {
            float av = ra[k];
            s0 = fmaf(av, se[b0 * 129 + k], s0);
            s1 = fmaf(av, se[b1 * 129 + k], s1);
        }
        float ap0 = -1e30f, ap1 = -1e30f, an0 = 0.0f, an1 = 0.0f;
        bool v0 = (b0 < m && b0 != a), v1 = (b1 < m && b1 != a);
        if (v0) { ap0 = -80.0f * fmaxf(1.4f - s0, 0.0f) * (s0 - 0.6f); an0 = an_exp(s0); }
        if (v1) { ap1 = -80.0f * fmaxf(1.4f - s1, 0.0f) * (s1 - 0.6f); an1 = an_exp(s1); }
        float mx = fmaxf(ap0, ap1);
        #pragma unroll
        for (int k = 16; k >= 1; k >>= 1) mx = fmaxf(mx, __shfl_xor_sync(0xffffffffu, mx, k));
        float es = (v0 ? __expf(ap0 - mx) : 0.0f) + (v1 ? __expf(ap1 - mx) : 0.0f);
        float sa = an0 + an1;
        #pragma unroll
        for (int k = 16; k >= 1; k >>= 1) {
            es += __shfl_xor_sync(0xffffffffu, es, k);
            sa += __shfl_xor_sync(0xffffffffu, sa, k);
        }
        if (lane == 0) {
            g_lsep[mlist[a]]    = mx + logf(es);
            g_samesum[mlist[a]] = sa;
        }
    }
}

// ---------------- persistent fused kernel ----------------------------------
#define SROW   144
#define ARR    (128 * SROW)       // 18432 B per array
#define STG    (2 * ARR)          // 36864 B per phase (A + B)
#define SMEM_SZ (2 * STG)         // 73728 B
#define NGRID  296                // 2 CTAs x 148 SMs, fully resident
#define NITEM  (2080 + NC)        // 2592 work items

// decode item w -> (isGemm, b or class id); R12's 1-in-5 interleave
__device__ __forceinline__ bool decode_item(int w, int* out) {
    if (w < 2560) {
        if (w % 5 == 4) { *out = w / 5; return false; }
        *out = w - w / 5;
        return true;
    }
    *out = w - NC;
    return true;
}

__device__ __forceinline__ void tri_decode(int b, int* pbi, int* pbj) {
    int r = (int)((__fsqrt_rn(8.0f * (float)b + 1.0f) - 1.0f) * 0.5f);
    while ((r + 1) * (r + 2) / 2 <= b) r++;
    while (r * (r + 1) / 2 > b) r--;
    *pbi = b - r * (r + 1) / 2;
    *pbj = r;
}

__device__ __forceinline__ void issue_loads(uint32_t sb, int rowBase, int colBase, int tid) {
    #pragma unroll
    for (int kc = 0; kc < 2; kc++) {
        uint32_t pb = sb + (uint32_t)kc * STG;
        #pragma unroll
        for (int it = 0; it < 4; it++) {
            int idx = it * 256 + tid;
            int row = idx >> 3, k8 = idx & 7;
            uint32_t so = (uint32_t)(row * SROW + k8 * 16);
            size_t gA = (size_t)(rowBase + row) * 16 + kc * 8 + k8;
            size_t gB = (size_t)(colBase + row) * 16 + kc * 8 + k8;
            cpa16(pb + so,       (const uint4*)g_h16 + gA);
            cpa16(pb + ARR + so, (const uint4*)g_h16 + gB);
        }
        asm volatile("cp.async.commit_group;" ::: "memory");
    }
}

__global__ void __launch_bounds__(256, 2) k_main_f() {
    extern __shared__ char sm[];
    uint32_t sb = smem_u32(sm);
    int tid = threadIdx.x;
    int lane = tid & 31, wid = tid >> 5;
    int g = lane >> 2, t = lane & 3;
    int wm = wid & 3, wn = wid >> 2;

    uint32_t lmo = (uint32_t)((lane & 15) * SROW + (lane >> 4) * 16);
    uint32_t aOff = (uint32_t)(wm * 32) * SROW + lmo;
    uint32_t bOff = (uint32_t)ARR + (uint32_t)(wn * 64) * SROW + lmo;

    bool prefetched = false;

    for (int w = blockIdx.x; w < NITEM; w += NGRID) {
        int id;
        bool isg = decode_item(w, &id);
        if (!isg) {
            // class item: no loads in flight (prefetch only precedes gemm items)
            __syncthreads();                 // quiesce any stragglers in smem
            class_block(id, sm);
            __syncthreads();
            continue;
        }
        int bi, bj;
        tri_decode(id, &bi, &bj);
        int rowBase = bi * 128, colBase = bj * 128;

        if (!prefetched) issue_loads(sb, rowBase, colBase, tid);

        float acc[2][8][4];
        #pragma unroll
        for (int i = 0; i < 2; i++)
            #pragma unroll
            for (int j = 0; j < 8; j++)
                #pragma unroll
                for (int e = 0; e < 4; e++) acc[i][j][e] = 0.0f;

        #pragma unroll
        for (int kc = 0; kc < 2; kc++) {
            if (kc == 0) asm volatile("cp.async.wait_group 1;" ::: "memory");
            else         asm volatile("cp.async.wait_group 0;" ::: "memory");
            __syncthreads();
            uint32_t pb = sb + (uint32_t)kc * STG;
            #pragma unroll
            for (int ks = 0; ks < 4; ks++) {
                uint32_t ko = (uint32_t)(ks * 32);
                uint32_t ah[2][4];
                ldsm4(ah[0], pb + aOff + ko);
                ldsm4(ah[1], pb + aOff + ko + 16 * SROW);
                #pragma unroll
                for (int jp = 0; jp < 4; jp++) {
                    uint32_t bh[4];
                    ldsm4(bh, pb + bOff + ko + (uint32_t)(jp * 16) * SROW);
                    mma_f16(acc[0][2 * jp],     ah[0], bh[0], bh[2]);
                    mma_f16(acc[1][2 * jp],     ah[1], bh[0], bh[2]);
                    mma_f16(acc[0][2 * jp + 1], ah[0], bh[1], bh[3]);
                    mma_f16(acc[1][2 * jp + 1], ah[1], bh[1], bh[3]);
                }
            }
        }
        __syncthreads();   // all ldsm reads done before buffers are overwritten

        // prefetch next item's tile if it is a GEMM tile; overlaps epilogue
        {
            int wn2 = w + NGRID;
            int idn;
            if (wn2 < NITEM && decode_item(wn2, &idn)) {
                int bin, bjn;
                tri_decode(idn, &bin, &bjn);
                issue_loads(sb, bin * 128, bjn * 128, tid);
                prefetched = true;
            } else {
                prefetched = false;
            }
        }

        // ---- epilogue (registers + global only; overlaps in-flight loads) ----
        bool diag = (bi == bj);
        #pragma unroll
        for (int i = 0; i < 2; i++)
            #pragma unroll
            for (int j = 0; j < 8; j++)
                #pragma unroll
                for (int e = 0; e < 4; e++) {
                    float x = an_exp(acc[i][j][e]);
                    if (diag) {
                        int rl = wm * 32 + i * 16 + g + ((e >> 1) << 3);
                        int cl = wn * 64 + j * 8 + 2 * t + (e & 1);
                        if (rl == cl) x = 0.0f;
                    }
                    acc[i][j][e] = x;
                }
        #pragma unroll
        for (int i = 0; i < 2; i++)
            #pragma unroll
            for (int h = 0; h < 2; h++) {
                float v = 0.0f;
                #pragma unroll
                for (int j = 0; j < 8; j++) v += acc[i][j][2 * h] + acc[i][j][2 * h + 1];
                v += __shfl_xor_sync(0xffffffffu, v, 1);
                v += __shfl_xor_sync(0xffffffffu, v, 2);
                if (t == 0)
                    atomicAdd(&g_sall[rowBase + wm * 32 + i * 16 + g + h * 8], v);
            }
        if (!diag) {
            #pragma unroll
            for (int j = 0; j < 8; j++)
                #pragma unroll
                for (int bb = 0; bb < 2; bb++) {
                    float v = acc[0][j][bb] + acc[0][j][2 + bb] +
                              acc[1][j][bb] + acc[1][j][2 + bb];
                    v += __shfl_xor_sync(0xffffffffu, v, 4);
                    v += __shfl_xor_sync(0xffffffffu, v, 8);
                    v += __shfl_xor_sync(0xffffffffu, v, 16);
                    if (g == 0)
                        atomicAdd(&g_sall[colBase + wn * 64 + j * 8 + 2 * t + bb], v);
                }
        }
    }
}

// ------- kernel 4 (fused): per-anchor finalize + last-block reduce ---------
__global__ void k_final_f(const void* __restrict__ lab, float* __restrict__ out) {
    __shared__ float ssum[256];
    __shared__ int   scnt[256];
    __shared__ int   s_last;
    int tid = threadIdx.x;
    int is64 = detect_is64(lab, tid);
    int i = blockIdx.x * 256 + tid;
    int c = is64 ? (int)((const long long*)lab)[i] : ((const int*)lab)[i];
    int m = g_cnt[c];
    int np = m - 1, nn = N - m;
    float sp = 0.0f;
    int ok = 0;
    if (np > 0 && nn > 0) {
        float sneg = g_sall[i] - g_samesum[i];
        sneg = fmaxf(sneg, 1e-30f);
        float x = g_lsep[i] + logf((float)nn) + logf(sneg) + logf((float)np);
        sp = (x > 0.0f) ? (x + log1pf(__expf(-x))) : log1pf(__expf(x));
        ok = 1;
    }
    ssum[tid] = sp; scnt[tid] = ok;
    __syncthreads();
    #pragma unroll
    for (int s = 128; s > 0; s >>= 1) {
        if (tid < s) { ssum[tid] += ssum[tid + s]; scnt[tid] += scnt[tid + s]; }
        __syncthreads();
    }
    if (tid == 0) {
        g_part[blockIdx.x] = ssum[0];
        g_pcnt[blockIdx.x] = scnt[0];
        __threadfence();
        unsigned v = atomicAdd(&g_done, 1u);
        s_last = (v == 31u);
    }
    __syncthreads();
    if (s_last) {
        if (tid < 32) {
            float v = *((volatile float*)&g_part[tid]);
            int   cc = *((volatile int*)&g_pcnt[tid]);
            #pragma unroll
            for (int k = 16; k >= 1; k >>= 1) {
                v  += __shfl_xor_sync(0xffffffffu, v, k);
                cc += __shfl_xor_sync(0xffffffffu, cc, k);
            }
            if (tid == 0) {
                out[0] = v / fmaxf((float)cc, 1.0f);
                g_done = 0;
            }
        }
        for (int q = tid; q < NC; q += 256) g_cnt[q] = 0;
    }
}

// ---------------- launch ---------------------------------------------------
extern "C" void kernel_launch(void* const* d_in, const int* in_sizes, int n_in,
                              void* d_out, int out_size) {
    const float* embeds = (const float*)d_in[0];
    const void*  labels = d_in[1];
    float* out = (float*)d_out;
    (void)in_sizes; (void)n_in; (void)out_size;

    cudaFuncSetAttribute(k_main_f, cudaFuncAttributeMaxDynamicSharedMemorySize, SMEM_SZ);

    k_norm<<<N / 8, 256>>>(embeds, labels);
    k_main_f<<<NGRID, 256, SMEM_SZ>>>();
    k_final_f<<<32, 256>>>(labels, out);
}

// round 17
// speedup vs baseline: 1.1698x; 1.1698x over previous
#include <cuda_runtime.h>
#include <cuda_fp16.h>
#include <math.h>
#include <stdint.h>

#define N 8192
#define D 128
#define NC 512
#define MAXM 64

// ---------------- scratch (device globals; no allocation allowed) ----------
__device__ __align__(16) float g_enorm[N * D];
__device__ __align__(16) __half g_h16[N * D];   // fp16(x)
__device__ int   g_cnt[NC];          // zeroed at module load; re-zeroed each run by k_final_f
__device__ int   g_members[NC * MAXM];
__device__ float g_lsep[N];
__device__ float g_samesum[N];
__device__ float g_sall[N];
__device__ float g_part[32];
__device__ int   g_pcnt[32];
__device__ unsigned g_done;          // zeroed at load; reset each run by k_final_f

// an_exp via ex2.approx with folded log2e
__device__ __forceinline__ float an_exp(float s) {
    float t = fmaxf(s + 0.4f, 0.0f);
    float x = 115.41560327111707f * t * (s - 0.4f);
    float r;
    asm("ex2.approx.f32 %0, %1;" : "=f"(r) : "f"(x));
    return r;
}

__device__ __forceinline__ uint32_t smem_u32(const void* p) {
    uint32_t a;
    asm("{ .reg .u64 t; cvta.to.shared.u64 t, %1; cvt.u32.u64 %0, t; }" : "=r"(a) : "l"(p));
    return a;
}
__device__ __forceinline__ void cpa16(uint32_t dst, const void* src) {
    asm volatile("cp.async.cg.shared.global [%0], [%1], 16;" :: "r"(dst), "l"(src) : "memory");
}
__device__ __forceinline__ void ldsm4(uint32_t* r, uint32_t addr) {
    asm volatile("ldmatrix.sync.aligned.m8n8.x4.shared.b16 {%0,%1,%2,%3}, [%4];"
        : "=r"(r[0]), "=r"(r[1]), "=r"(r[2]), "=r"(r[3]) : "r"(addr));
}
__device__ __forceinline__ void mma_f16(float* d, const uint32_t* a, uint32_t b0, uint32_t b1) {
    asm volatile(
        "mma.sync.aligned.m16n8k16.row.col.f32.f16.f16.f32 "
        "{%0,%1,%2,%3}, {%4,%5,%6,%7}, {%8,%9}, {%0,%1,%2,%3};\n"
        : "+f"(d[0]), "+f"(d[1]), "+f"(d[2]), "+f"(d[3])
        : "r"(a[0]), "r"(a[1]), "r"(a[2]), "r"(a[3]), "r"(b0), "r"(b1));
}

// per-block label dtype detect: int64 labels have all odd 32-bit words == 0
__device__ __forceinline__ int detect_is64(const void* lab, int tid) {
    int w = (tid < 64) ? ((const int*)lab)[2 * tid + 1] : 0;
    return !__syncthreads_or(w != 0);
}

// ---------------- kernel 1: normalize + fp16 + class lists (R12 proven) ----
__global__ void k_norm(const float* __restrict__ in, const void* __restrict__ lab) {
    int tid = threadIdx.x;
    int is64 = detect_is64(lab, tid);
    int gid = blockIdx.x * blockDim.x + tid;
    if (gid < N) g_sall[gid] = 0.0f;
    int row  = blockIdx.x * 8 + (tid >> 5);
    int lane = tid & 31;
    float4 v = *(const float4*)(in + row * D + lane * 4);
    float ss = v.x * v.x + v.y * v.y + v.z * v.z + v.w * v.w;
    #pragma unroll
    for (int m = 16; m >= 1; m >>= 1) ss += __shfl_xor_sync(0xffffffffu, ss, m);
    float inv = 1.0f / fmaxf(sqrtf(ss), 1e-12f);
    float o[4] = {v.x * inv, v.y * inv, v.z * inv, v.w * inv};
    float4 of; of.x = o[0]; of.y = o[1]; of.z = o[2]; of.w = o[3];
    *(float4*)(g_enorm + row * D + lane * 4) = of;
    *(__half2*)(g_h16 + row * D + lane * 4)     = __floats2half2_rn(o[0], o[1]);
    *(__half2*)(g_h16 + row * D + lane * 4 + 2) = __floats2half2_rn(o[2], o[3]);
    if (lane == 0) {
        int c = is64 ? (int)((const long long*)lab)[row] : ((const int*)lab)[row];
        int p = atomicAdd(&g_cnt[c], 1);
        if (p < MAXM) g_members[c * MAXM + p] = row;
    }
}

// ---------------- class block body (runs inside k_main_f) ------------------
__device__ void class_block(int c, char* smraw) {
    int*   mlist = (int*)smraw;
    float* se    = (float*)(smraw + 256);
    int m = g_cnt[c];
    if (m > MAXM) m = MAXM;
    if (m == 0) return;
    int tid = threadIdx.x, lane = tid & 31, wid = tid >> 5;
    if (tid < m) mlist[tid] = g_members[c * MAXM + tid];
    __syncthreads();
    for (int p = tid; p < m * D; p += 256) {
        int r = p >> 7, k = p & 127;
        se[r * 129 + k] = g_enorm[mlist[r] * D + k];
    }
    __syncthreads();
    for (int a = wid; a < m; a += 8) {
        int b0 = lane, b1 = lane + 32;
        float s0 = 0.0f, s1 = 0.0f;
        const float* ra = se + a * 129;
        #pragma unroll 8
        for (int k = 0; k < D; k++) {
            float av = ra[k];
            s0 = fmaf(av, se[b0 * 129 + k], s0);
            s1 = fmaf(av, se[b1 * 129 + k], s1);
        }
        float ap0 = -1e30f, ap1 = -1e30f, an0 = 0.0f, an1 = 0.0f;
        bool v0 = (b0 < m && b0 != a), v1 = (b1 < m && b1 != a);
        if (v0) { ap0 = -80.0f * fmaxf(1.4f - s0, 0.0f) * (s0 - 0.6f); an0 = an_exp(s0); }
        if (v1) { ap1 = -80.0f * fmaxf(1.4f - s1, 0.0f) * (s1 - 0.6f); an1 = an_exp(s1); }
        float mx = fmaxf(ap0, ap1);
        #pragma unroll
        for (int k = 16; k >= 1; k >>= 1) mx = fmaxf(mx, __shfl_xor_sync(0xffffffffu, mx, k));
        float es = (v0 ? __expf(ap0 - mx) : 0.0f) + (v1 ? __expf(ap1 - mx) : 0.0f);
        float sa = an0 + an1;
        #pragma unroll
        for (int k = 16; k >= 1; k >>= 1) {
            es += __shfl_xor_sync(0xffffffffu, es, k);
            sa += __shfl_xor_sync(0xffffffffu, sa, k);
        }
        if (lane == 0) {
            g_lsep[mlist[a]]    = mx + logf(es);
            g_samesum[mlist[a]] = sa;
        }
    }
}

// ---- kernel 3 (fused): GEMM tiles + class blocks, interleaved 1-in-5 ------
// N-split (two 32-col halves per warp) -> acc 32 regs -> 3 CTAs/SM.
#define SROW   144
#define ARR    (128 * SROW)       // 18432 B per array
#define STG    (2 * ARR)          // 36864 B per phase (A + B)
#define SMEM_SZ (2 * STG)         // 73728 B
#define NBLK   (2080 + NC)        // 2592

__global__ void __launch_bounds__(256, 3) k_main_f() {
    extern __shared__ char sm[];
    int blk = blockIdx.x;
    int b;
    if (blk < 2560) {
        if (blk % 5 == 4) { class_block(blk / 5, sm); return; }
        b = blk - blk / 5;
    } else {
        b = blk - NC;
    }

    int r = (int)((__fsqrt_rn(8.0f * (float)b + 1.0f) - 1.0f) * 0.5f);
    while ((r + 1) * (r + 2) / 2 <= b) r++;
    while (r * (r + 1) / 2 > b) r--;
    int bi = b - r * (r + 1) / 2;
    int bj = r;

    uint32_t sb = smem_u32(sm);
    int tid = threadIdx.x;
    int lane = tid & 31, wid = tid >> 5;
    int g = lane >> 2, t = lane & 3;
    int wm = wid & 3, wn = wid >> 2;
    int rowBase = bi * 128, colBase = bj * 128;

    uint32_t lmo = (uint32_t)((lane & 15) * SROW + (lane >> 4) * 16);
    uint32_t aOff = (uint32_t)(wm * 32) * SROW + lmo;
    uint32_t bOff = (uint32_t)ARR + (uint32_t)(wn * 64) * SROW + lmo;

    // prologue: both phases' loads up front (two commit groups)
    #pragma unroll
    for (int kc = 0; kc < 2; kc++) {
        uint32_t pb = sb + (uint32_t)kc * STG;
        #pragma unroll
        for (int it = 0; it < 4; it++) {
            int idx = it * 256 + tid;
            int row = idx >> 3, k8 = idx & 7;
            uint32_t so = (uint32_t)(row * SROW + k8 * 16);
            size_t gA = (size_t)(rowBase + row) * 16 + kc * 8 + k8;
            size_t gB = (size_t)(colBase + row) * 16 + kc * 8 + k8;
            cpa16(pb + so,       (const uint4*)g_h16 + gA);
            cpa16(pb + ARR + so, (const uint4*)g_h16 + gB);
        }
        asm volatile("cp.async.commit_group;" ::: "memory");
    }

    bool diag = (bi == bj);
    float rs[2][2];
    rs[0][0] = rs[0][1] = rs[1][0] = rs[1][1] = 0.0f;

    #pragma unroll
    for (int half = 0; half < 2; half++) {
        float acc[2][4][4];
        #pragma unroll
        for (int i = 0; i < 2; i++)
            #pragma unroll
            for (int jj = 0; jj < 4; jj++)
                #pragma unroll
                for (int e = 0; e < 4; e++) acc[i][jj][e] = 0.0f;

        #pragma unroll
        for (int kc = 0; kc < 2; kc++) {
            if (half == 0) {
                if (kc == 0) asm volatile("cp.async.wait_group 1;" ::: "memory");
                else         asm volatile("cp.async.wait_group 0;" ::: "memory");
                __syncthreads();
            }
            uint32_t pb = sb + (uint32_t)kc * STG;
            #pragma unroll
            for (int ks = 0; ks < 4; ks++) {
                uint32_t ko = (uint32_t)(ks * 32);
                uint32_t ah[2][4];
                ldsm4(ah[0], pb + aOff + ko);
                ldsm4(ah[1], pb + aOff + ko + 16 * SROW);
                #pragma unroll
                for (int jq = 0; jq < 2; jq++) {
                    int jp = half * 2 + jq;
                    uint32_t bh[4];
                    ldsm4(bh, pb + bOff + ko + (uint32_t)(jp * 16) * SROW);
                    mma_f16(acc[0][2 * jq],     ah[0], bh[0], bh[2]);
                    mma_f16(acc[1][2 * jq],     ah[1], bh[0], bh[2]);
                    mma_f16(acc[0][2 * jq + 1], ah[0], bh[1], bh[3]);
                    mma_f16(acc[1][2 * jq + 1], ah[1], bh[1], bh[3]);
                }
            }
        }

        // ---- epilogue for this half (cols wn*64 + (half*4+jj)*8 + ...) ----
        #pragma unroll
        for (int i = 0; i < 2; i++)
            #pragma unroll
            for (int jj = 0; jj < 4; jj++)
                #pragma unroll
                for (int e = 0; e < 4; e++) {
                    float x = an_exp(acc[i][jj][e]);
                    if (diag) {
                        int rl = wm * 32 + i * 16 + g + ((e >> 1) << 3);
                        int cl = wn * 64 + (half * 4 + jj) * 8 + 2 * t + (e & 1);
                        if (rl == cl) x = 0.0f;
                    }
                    acc[i][jj][e] = x;
                }
        #pragma unroll
        for (int i = 0; i < 2; i++)
            #pragma unroll
            for (int h = 0; h < 2; h++) {
                float v = 0.0f;
                #pragma unroll
                for (int jj = 0; jj < 4; jj++) v += acc[i][jj][2 * h] + acc[i][jj][2 * h + 1];
                rs[i][h] += v;
            }
        if (!diag) {
            #pragma unroll
            for (int jj = 0; jj < 4; jj++)
                #pragma unroll
                for (int bb = 0; bb < 2; bb++) {
                    float v = acc[0][jj][bb] + acc[0][jj][2 + bb] +
                              acc[1][jj][bb] + acc[1][jj][2 + bb];
                    v += __shfl_xor_sync(0xffffffffu, v, 4);
                    v += __shfl_xor_sync(0xffffffffu, v, 8);
                    v += __shfl_xor_sync(0xffffffffu, v, 16);
                    if (g == 0)
                        atomicAdd(&g_sall[colBase + wn * 64 + (half * 4 + jj) * 8 + 2 * t + bb], v);
                }
        }
    }

    // row sums (carried across both halves)
    #pragma unroll
    for (int i = 0; i < 2; i++)
        #pragma unroll
        for (int h = 0; h < 2; h++) {
            float v = rs[i][h];
            v += __shfl_xor_sync(0xffffffffu, v, 1);
            v += __shfl_xor_sync(0xffffffffu, v, 2);
            if (t == 0)
                atomicAdd(&g_sall[rowBase + wm * 32 + i * 16 + g + h * 8], v);
        }
}

// ------- kernel 4 (fused): per-anchor finalize + last-block reduce ---------
__global__ void k_final_f(const void* __restrict__ lab, float* __restrict__ out) {
    __shared__ float ssum[256];
    __shared__ int   scnt[256];
    __shared__ int   s_last;
    int tid = threadIdx.x;
    int is64 = detect_is64(lab, tid);
    int i = blockIdx.x * 256 + tid;
    int c = is64 ? (int)((const long long*)lab)[i] : ((const int*)lab)[i];
    int m = g_cnt[c];
    int np = m - 1, nn = N - m;
    float sp = 0.0f;
    int ok = 0;
    if (np > 0 && nn > 0) {
        float sneg = g_sall[i] - g_samesum[i];
        sneg = fmaxf(sneg, 1e-30f);
        float x = g_lsep[i] + logf((float)nn) + logf(sneg) + logf((float)np);
        sp = (x > 0.0f) ? (x + log1pf(__expf(-x))) : log1pf(__expf(x));
        ok = 1;
    }
    ssum[tid] = sp; scnt[tid] = ok;
    __syncthreads();
    #pragma unroll
    for (int s = 128; s > 0; s >>= 1) {
        if (tid < s) { ssum[tid] += ssum[tid + s]; scnt[tid] += scnt[tid + s]; }
        __syncthreads();
    }
    if (tid == 0) {
        g_part[blockIdx.x] = ssum[0];
        g_pcnt[blockIdx.x] = scnt[0];
        __threadfence();
        unsigned v = atomicAdd(&g_done, 1u);
        s_last = (v == 31u);
    }
    __syncthreads();
    if (s_last) {
        if (tid < 32) {
            float v = *((volatile float*)&g_part[tid]);
            int   cc = *((volatile int*)&g_pcnt[tid]);
            #pragma unroll
            for (int k = 16; k >= 1; k >>= 1) {
                v  += __shfl_xor_sync(0xffffffffu, v, k);
                cc += __shfl_xor_sync(0xffffffffu, cc, k);
            }
            if (tid == 0) {
                out[0] = v / fmaxf((float)cc, 1.0f);
                g_done = 0;
            }
        }
        for (int q = tid; q < NC; q += 256) g_cnt[q] = 0;
    }
}

// ---------------- launch ---------------------------------------------------
extern "C" void kernel_launch(void* const* d_in, const int* in_sizes, int n_in,
                              void* d_out, int out_size) {
    const float* embeds = (const float*)d_in[0];
    const void*  labels = d_in[1];
    float* out = (float*)d_out;
    (void)in_sizes; (void)n_in; (void)out_size;

    cudaFuncSetAttribute(k_main_f, cudaFuncAttributeMaxDynamicSharedMemorySize, SMEM_SZ);

    k_norm<<<N / 8, 256>>>(embeds, labels);
    k_main_f<<<NBLK, 256, SMEM_SZ>>>();
    k_final_f<<<32, 256>>>(labels, out);
}